// round 6
// baseline (speedup 1.0000x reference)
#include <cuda_runtime.h>
#include <math.h>

#define T_SEQ 4096
#define HID   2048
#define QH    16
#define KVH   4
#define HD    128
#define WIN   512

// ---------------- scratch (device globals; no allocations allowed) --------
__device__ float g_Qraw[T_SEQ * HID];
__device__ float g_Kraw[T_SEQ * KVH * HD];
__device__ float g_V   [T_SEQ * KVH * HD];
__device__ float g_Qt  [QH  * HD * T_SEQ];   // [h][d][t]
__device__ float g_Kt  [KVH * HD * T_SEQ];   // [g][d][t]
__device__ float g_AO  [T_SEQ * HID];

// ---------------- SGEMM: C[M,N] = A[M,K] * B[N,K]^T  (both row-major) -----
#define GBM 128
#define GBN 128
#define GBK 8

__global__ __launch_bounds__(256) void sgemm_nt(
    const float* __restrict__ A, const float* __restrict__ B,
    float* __restrict__ C, int M, int N, int K)
{
    __shared__ float As[GBK][GBM];
    __shared__ float Bs[GBK][GBN];
    const int tid = threadIdx.x;
    const int tx = tid & 15, ty = tid >> 4;
    const int bm = blockIdx.y * GBM, bn = blockIdx.x * GBN;

    const int lr = tid >> 1;           // 0..127 tile row
    const int lc = (tid & 1) << 2;     // 0 or 4 (k offset)
    const float* Ap = A + (size_t)(bm + lr) * K + lc;
    const float* Bp = B + (size_t)(bn + lr) * K + lc;

    float4 ar = *(const float4*)Ap;
    float4 br = *(const float4*)Bp;

    float acc[8][8];
#pragma unroll
    for (int i = 0; i < 8; ++i)
#pragma unroll
        for (int j = 0; j < 8; ++j) acc[i][j] = 0.f;

    const int nk = K / GBK;
    for (int kt = 0; kt < nk; ++kt) {
        As[lc + 0][lr] = ar.x; As[lc + 1][lr] = ar.y;
        As[lc + 2][lr] = ar.z; As[lc + 3][lr] = ar.w;
        Bs[lc + 0][lr] = br.x; Bs[lc + 1][lr] = br.y;
        Bs[lc + 2][lr] = br.z; Bs[lc + 3][lr] = br.w;
        __syncthreads();
        if (kt + 1 < nk) {
            ar = *(const float4*)(Ap + (size_t)(kt + 1) * GBK);
            br = *(const float4*)(Bp + (size_t)(kt + 1) * GBK);
        }
#pragma unroll
        for (int k = 0; k < GBK; ++k) {
            float a[8], b[8];
            *(float4*)&a[0] = *(const float4*)&As[k][ty * 8];
            *(float4*)&a[4] = *(const float4*)&As[k][ty * 8 + 4];
            *(float4*)&b[0] = *(const float4*)&Bs[k][tx * 8];
            *(float4*)&b[4] = *(const float4*)&Bs[k][tx * 8 + 4];
#pragma unroll
            for (int i = 0; i < 8; ++i)
#pragma unroll
                for (int j = 0; j < 8; ++j)
                    acc[i][j] = fmaf(a[i], b[j], acc[i][j]);
        }
        __syncthreads();
    }
#pragma unroll
    for (int i = 0; i < 8; ++i) {
        float* cp = C + (size_t)(bm + ty * 8 + i) * N + bn + tx * 8;
        *(float4*)cp       = make_float4(acc[i][0], acc[i][1], acc[i][2], acc[i][3]);
        *(float4*)(cp + 4) = make_float4(acc[i][4], acc[i][5], acc[i][6], acc[i][7]);
    }
}

// ------------- RoPE + transpose: src[T][heads*128] -> dst[heads][128][T] --
__global__ __launch_bounds__(256) void rope_transpose(
    const float* __restrict__ src, float* __restrict__ dst,
    int heads, float scale)
{
    __shared__ float As[32][33];
    __shared__ float Bs[32][33];
    const int h  = blockIdx.z;
    const int t0 = blockIdx.x << 5;
    const int d0 = blockIdx.y << 5;          // 0 or 32 (within first half)
    const int tx  = threadIdx.x & 31;
    const int tyb = threadIdx.x >> 5;        // 0..7
    const int stride = heads * HD;
#pragma unroll
    for (int it = 0; it < 4; ++it) {
        int r = tyb + (it << 3);
        const float* p = src + (size_t)(t0 + r) * stride + h * HD + d0 + tx;
        As[r][tx] = p[0];
        Bs[r][tx] = p[64];
    }
    __syncthreads();
#pragma unroll
    for (int it = 0; it < 4; ++it) {
        int dl = tyb + (it << 3);
        int d  = d0 + dl;                    // 0..63
        int t  = t0 + tx;
        float inv_freq = powf(10000.0f, -(float)d * (1.0f / 64.0f));
        float ang = (float)t * inv_freq;
        float s, c;
        sincosf(ang, &s, &c);
        float x1 = As[tx][dl];
        float x2 = Bs[tx][dl];
        dst[(size_t)(h * HD + d)      * T_SEQ + t] = (x1 * c - x2 * s) * scale;
        dst[(size_t)(h * HD + d + 64) * T_SEQ + t] = (x1 * s + x2 * c) * scale;
    }
}

// ---------------- flash attention, sliding window + causal ---------------
#define PADQ 68
#define ATTN_SMEM ((128 * PADQ + 128 * PADQ + 64 * HD + 64 * PADQ) * 4)

__device__ __forceinline__ float rmax16(float v) {
    v = fmaxf(v, __shfl_xor_sync(0xffffffffu, v, 8));
    v = fmaxf(v, __shfl_xor_sync(0xffffffffu, v, 4));
    v = fmaxf(v, __shfl_xor_sync(0xffffffffu, v, 2));
    v = fmaxf(v, __shfl_xor_sync(0xffffffffu, v, 1));
    return v;
}
__device__ __forceinline__ float rsum16(float v) {
    v += __shfl_xor_sync(0xffffffffu, v, 8);
    v += __shfl_xor_sync(0xffffffffu, v, 4);
    v += __shfl_xor_sync(0xffffffffu, v, 2);
    v += __shfl_xor_sync(0xffffffffu, v, 1);
    return v;
}

__global__ __launch_bounds__(256) void attn_kernel(
    const float* __restrict__ Qt,   // [QH][HD][T]
    const float* __restrict__ Kt,   // [KVH][HD][T]
    const float* __restrict__ V,    // [T][KVH*HD]
    float* __restrict__ O)          // [T][QH*HD]
{
    extern __shared__ float sm[];
    float* Qs = sm;                 // [128][PADQ]  (d-major)
    float* Ks = Qs + 128 * PADQ;    // [128][PADQ]
    float* Vs = Ks + 128 * PADQ;    // [64][128]    (row-major)
    float* Ps = Vs + 64 * HD;       // [64][PADQ]

    const int h  = blockIdx.y;
    const int g  = h >> 2;          // kv head (reps = 4)
    const int qs = blockIdx.x << 6;
    const int tid = threadIdx.x;
    const int tx = tid & 15, ty = tid >> 4;

    // load Q tile: Qs[d][r] = Qt[h][d][qs+r]
    const float* qbase = Qt + (size_t)h * HD * T_SEQ + qs;
    for (int i = tid; i < 128 * 16; i += 256) {
        int d = i >> 4, r4 = (i & 15) << 2;
        *(float4*)&Qs[d * PADQ + r4] = *(const float4*)(qbase + (size_t)d * T_SEQ + r4);
    }

    float m[4], l[4], o[4][8];
#pragma unroll
    for (int i = 0; i < 4; ++i) {
        m[i] = -1e30f; l[i] = 0.f;
#pragma unroll
        for (int jj = 0; jj < 8; ++jj) o[i][jj] = 0.f;
    }

    const int kb0 = (qs >= WIN) ? ((qs - WIN) >> 6) : 0;
    const int kb1 = qs >> 6;

    for (int kb = kb0; kb <= kb1; ++kb) {
        const int ks0 = kb << 6;
        __syncthreads();   // prior PV reads done before Ks/Vs overwrite
        const float* kbase = Kt + (size_t)g * HD * T_SEQ + ks0;
        for (int i = tid; i < 128 * 16; i += 256) {
            int d = i >> 4, r4 = (i & 15) << 2;
            *(float4*)&Ks[d * PADQ + r4] = *(const float4*)(kbase + (size_t)d * T_SEQ + r4);
        }
        const float* vbase = V + (size_t)ks0 * (KVH * HD) + g * HD;
        for (int i = tid; i < 64 * 32; i += 256) {
            int r = i >> 5, d4 = (i & 31) << 2;
            *(float4*)&Vs[r * HD + d4] = *(const float4*)(vbase + (size_t)r * (KVH * HD) + d4);
        }
        __syncthreads();

        // S = Q.K^T (64x64), 4x4 fragment per thread
        float s[4][4];
#pragma unroll
        for (int i = 0; i < 4; ++i)
#pragma unroll
            for (int j = 0; j < 4; ++j) s[i][j] = 0.f;
#pragma unroll 4
        for (int k = 0; k < HD; ++k) {
            float a[4], b[4];
            *(float4*)a = *(const float4*)&Qs[k * PADQ + (ty << 2)];
            *(float4*)b = *(const float4*)&Ks[k * PADQ + (tx << 2)];
#pragma unroll
            for (int i = 0; i < 4; ++i)
#pragma unroll
                for (int j = 0; j < 4; ++j)
                    s[i][j] = fmaf(a[i], b[j], s[i][j]);
        }

        // mask + online softmax
#pragma unroll
        for (int i = 0; i < 4; ++i) {
            const int t = qs + (ty << 2) + i;
            float rm = -1e30f;
#pragma unroll
            for (int j = 0; j < 4; ++j) {
                int kj = ks0 + (tx << 2) + j;
                bool valid = (kj <= t) && (t - kj <= WIN);
                if (!valid) s[i][j] = -1e30f;
                rm = fmaxf(rm, s[i][j]);
            }
            rm = rmax16(rm);
            float mn   = fmaxf(m[i], rm);
            float corr = __expf(m[i] - mn);
            float sum = 0.f;
#pragma unroll
            for (int j = 0; j < 4; ++j) {
                float p = (s[i][j] > -1e29f) ? __expf(s[i][j] - mn) : 0.f;
                Ps[((ty << 2) + i) * PADQ + (tx << 2) + j] = p;
                sum += p;
            }
            sum = rsum16(sum);
            l[i] = l[i] * corr + sum;
            m[i] = mn;
#pragma unroll
            for (int jj = 0; jj < 8; ++jj) o[i][jj] *= corr;
        }
        __syncthreads();

        // O += P.V  (rows ty*4+i, dims tx*8+jj)
#pragma unroll 2
        for (int j = 0; j < 64; ++j) {
            float v[8];
            *(float4*)&v[0] = *(const float4*)&Vs[j * HD + (tx << 3)];
            *(float4*)&v[4] = *(const float4*)&Vs[j * HD + (tx << 3) + 4];
#pragma unroll
            for (int i = 0; i < 4; ++i) {
                float p = Ps[((ty << 2) + i) * PADQ + j];
#pragma unroll
                for (int jj = 0; jj < 8; ++jj)
                    o[i][jj] = fmaf(p, v[jj], o[i][jj]);
            }
        }
    }

#pragma unroll
    for (int i = 0; i < 4; ++i) {
        float inv = 1.0f / l[i];
        int t = qs + (ty << 2) + i;
        float* op = O + (size_t)t * HID + h * HD + (tx << 3);
        *(float4*)op       = make_float4(o[i][0] * inv, o[i][1] * inv, o[i][2] * inv, o[i][3] * inv);
        *(float4*)(op + 4) = make_float4(o[i][4] * inv, o[i][5] * inv, o[i][6] * inv, o[i][7] * inv);
    }
}

// --------------------------------------------------------------------------
extern "C" void kernel_launch(void* const* d_in, const int* in_sizes, int n_in,
                              void* d_out, int out_size)
{
    const float* x  = (const float*)d_in[0];
    const float* wq = (const float*)d_in[1];
    const float* wk = (const float*)d_in[2];
    const float* wv = (const float*)d_in[3];
    const float* wo = (const float*)d_in[4];
    float* out = (float*)d_out;

    float *qraw, *kraw, *v, *qt, *kt, *ao;
    cudaGetSymbolAddress((void**)&qraw, g_Qraw);
    cudaGetSymbolAddress((void**)&kraw, g_Kraw);
    cudaGetSymbolAddress((void**)&v,    g_V);
    cudaGetSymbolAddress((void**)&qt,   g_Qt);
    cudaGetSymbolAddress((void**)&kt,   g_Kt);
    cudaGetSymbolAddress((void**)&ao,   g_AO);

    cudaFuncSetAttribute(attn_kernel,
                         cudaFuncAttributeMaxDynamicSharedMemorySize, ATTN_SMEM);

    dim3 blk(256);
    // projections
    sgemm_nt<<<dim3(HID / GBN,      T_SEQ / GBM), blk>>>(x, wq, qraw, T_SEQ, HID,      HID);
    sgemm_nt<<<dim3(KVH * HD / GBN, T_SEQ / GBM), blk>>>(x, wk, kraw, T_SEQ, KVH * HD, HID);
    sgemm_nt<<<dim3(KVH * HD / GBN, T_SEQ / GBM), blk>>>(x, wv, v,    T_SEQ, KVH * HD, HID);
    // RoPE + transpose (scale 1/sqrt(HD) folded into Q)
    rope_transpose<<<dim3(T_SEQ / 32, 2, QH),  blk>>>(qraw, qt, QH,  0.08838834764831845f);
    rope_transpose<<<dim3(T_SEQ / 32, 2, KVH), blk>>>(kraw, kt, KVH, 1.0f);
    // attention
    attn_kernel<<<dim3(T_SEQ / 64, QH), blk, ATTN_SMEM>>>(qt, kt, v, ao);
    // output projection
    sgemm_nt<<<dim3(HID / GBN, T_SEQ / GBM), blk>>>(ao, wo, out, T_SEQ, HID, HID);
}

// round 8
// speedup vs baseline: 1.8570x; 1.8570x over previous
#include <cuda_runtime.h>
#include <cuda_bf16.h>
#include <math.h>
#include <stdint.h>

#define T_SEQ 4096
#define HID   2048
#define QH    16
#define KVH   4
#define HD    128
#define WIN   512

// ---------------- scratch (device globals; no allocations allowed) --------
__device__ float g_Qraw[T_SEQ * HID];
__device__ float g_Kraw[T_SEQ * KVH * HD];
__device__ float g_V   [T_SEQ * KVH * HD];
__device__ float g_Qt  [QH  * HD * T_SEQ];   // [h][d][t]
__device__ float g_Kt  [KVH * HD * T_SEQ];   // [g][d][t]
__device__ float g_AO  [T_SEQ * HID];

// bf16 hi/lo split operands
__device__ __nv_bfloat16 g_xh [T_SEQ * HID],      g_xl [T_SEQ * HID];
__device__ __nv_bfloat16 g_wqh[HID * HID],        g_wql[HID * HID];
__device__ __nv_bfloat16 g_wkh[KVH * HD * HID],   g_wkl[KVH * HD * HID];
__device__ __nv_bfloat16 g_wvh[KVH * HD * HID],   g_wvl[KVH * HD * HID];
__device__ __nv_bfloat16 g_woh[HID * HID],        g_wol[HID * HID];
__device__ __nv_bfloat16 g_aoh[T_SEQ * HID],      g_aol[T_SEQ * HID];

// ---------------- split fp32 -> bf16 hi + bf16 lo -------------------------
__global__ __launch_bounds__(256) void split_bf16(
    const float4* __restrict__ src,
    __nv_bfloat162* __restrict__ hi, __nv_bfloat162* __restrict__ lo, int n4)
{
    int i = blockIdx.x * blockDim.x + threadIdx.x;
    if (i >= n4) return;
    float4 f = src[i];
    __nv_bfloat16 h0 = __float2bfloat16(f.x);
    __nv_bfloat16 h1 = __float2bfloat16(f.y);
    __nv_bfloat16 h2 = __float2bfloat16(f.z);
    __nv_bfloat16 h3 = __float2bfloat16(f.w);
    __nv_bfloat162 a, b;
    a.x = h0; a.y = h1; b.x = h2; b.y = h3;
    hi[2 * i] = a; hi[2 * i + 1] = b;
    a.x = __float2bfloat16(f.x - __bfloat162float(h0));
    a.y = __float2bfloat16(f.y - __bfloat162float(h1));
    b.x = __float2bfloat16(f.z - __bfloat162float(h2));
    b.y = __float2bfloat16(f.w - __bfloat162float(h3));
    lo[2 * i] = a; lo[2 * i + 1] = b;
}

// ---------------- tensor-core GEMM: C[M,N] = A[M,K] * B[N,K]^T ------------
// bf16 3-product split: Ah*Bh + Ah*Bl + Al*Bh, fp32 accumulate.
#define PADK 72                                 // bf16 elems per smem row
#define TILE_BYTES (128 * PADK * 2)             // one 128x64 operand tile
#define STAGE_BYTES (4 * TILE_BYTES)
#define SMEM_TC (2 * STAGE_BYTES)               // double buffered = 147456 B

__device__ __forceinline__ void cp16(uint32_t dst, const void* src) {
    asm volatile("cp.async.cg.shared.global [%0], [%1], 16;\n" :: "r"(dst), "l"(src));
}
#define CP_COMMIT() asm volatile("cp.async.commit_group;\n")
#define CP_WAIT0()  asm volatile("cp.async.wait_group 0;\n")

#define LDSM4(r, addr) \
    asm volatile("ldmatrix.sync.aligned.m8n8.x4.shared.b16 {%0,%1,%2,%3}, [%4];" \
        : "=r"((r)[0]), "=r"((r)[1]), "=r"((r)[2]), "=r"((r)[3]) : "r"(addr))

#define MMA_BF16(d, a, b0, b1) \
    asm volatile("mma.sync.aligned.m16n8k16.row.col.f32.bf16.bf16.f32 " \
        "{%0,%1,%2,%3}, {%4,%5,%6,%7}, {%8,%9}, {%0,%1,%2,%3};" \
        : "+f"((d)[0]), "+f"((d)[1]), "+f"((d)[2]), "+f"((d)[3]) \
        : "r"((a)[0]), "r"((a)[1]), "r"((a)[2]), "r"((a)[3]), "r"(b0), "r"(b1))

__global__ __launch_bounds__(256) void gemm_tc(
    const __nv_bfloat16* __restrict__ Ah, const __nv_bfloat16* __restrict__ Al,
    const __nv_bfloat16* __restrict__ Bh, const __nv_bfloat16* __restrict__ Bl,
    float* __restrict__ C, int M, int N, int K)
{
    extern __shared__ char smem_raw[];
    const uint32_t smem_base = (uint32_t)__cvta_generic_to_shared(smem_raw);
    const int tid = threadIdx.x;
    const int lane = tid & 31, warp = tid >> 5;
    const int wm = (warp >> 1) << 5;          // 0,32,64,96
    const int wn = (warp & 1) << 6;           // 0,64
    const int bm = blockIdx.y << 7, bn = blockIdx.x << 7;

    // global-load assignment: thread covers rows lrow+{0,32,64,96}, 16B of cols
    const int lrow = tid >> 3;                // 0..31
    const int lcol = (tid & 7) << 3;          // bf16 col 0..56

    const __nv_bfloat16* pAh = Ah + (size_t)(bm + lrow) * K + lcol;
    const __nv_bfloat16* pAl = Al + (size_t)(bm + lrow) * K + lcol;
    const __nv_bfloat16* pBh = Bh + (size_t)(bn + lrow) * K + lcol;
    const __nv_bfloat16* pBl = Bl + (size_t)(bn + lrow) * K + lcol;
    const uint32_t sdst0 = smem_base + (uint32_t)(lrow * PADK + lcol) * 2;

    float acc[2][8][4];
#pragma unroll
    for (int i = 0; i < 2; ++i)
#pragma unroll
        for (int j = 0; j < 8; ++j)
#pragma unroll
            for (int q = 0; q < 4; ++q) acc[i][j][q] = 0.f;

    const int nkb = K >> 6;

    // prologue: stage 0
    {
        uint32_t sb = sdst0;
#pragma unroll
        for (int p = 0; p < 4; ++p) {
            size_t go = (size_t)(p << 5) * K;
            uint32_t so = sb + (uint32_t)(p << 5) * PADK * 2;
            cp16(so + 0 * TILE_BYTES, pAh + go);
            cp16(so + 1 * TILE_BYTES, pAl + go);
            cp16(so + 2 * TILE_BYTES, pBh + go);
            cp16(so + 3 * TILE_BYTES, pBl + go);
        }
        CP_COMMIT();
    }

    // ldmatrix per-thread address components
    const int a_row  = wm + (lane & 15);
    const int a_koff = (lane >> 4) << 3;
    const int b_row  = wn + (lane & 7) + ((lane & 16) >> 1);
    const int b_koff = ((lane >> 3) & 1) << 3;

    for (int kb = 0; kb < nkb; ++kb) {
        CP_WAIT0();
        __syncthreads();

        if (kb + 1 < nkb) {
            const int k0 = (kb + 1) << 6;
            uint32_t sb = sdst0 + ((kb + 1) & 1) * STAGE_BYTES;
#pragma unroll
            for (int p = 0; p < 4; ++p) {
                size_t go = (size_t)(p << 5) * K + k0;
                uint32_t so = sb + (uint32_t)(p << 5) * PADK * 2;
                cp16(so + 0 * TILE_BYTES, pAh + go);
                cp16(so + 1 * TILE_BYTES, pAl + go);
                cp16(so + 2 * TILE_BYTES, pBh + go);
                cp16(so + 3 * TILE_BYTES, pBl + go);
            }
            CP_COMMIT();
        }

        const uint32_t sb  = smem_base + (kb & 1) * STAGE_BYTES;
        const uint32_t sAh = sb;
        const uint32_t sAl = sb + 1 * TILE_BYTES;
        const uint32_t sBh = sb + 2 * TILE_BYTES;
        const uint32_t sBl = sb + 3 * TILE_BYTES;

#pragma unroll
        for (int ks = 0; ks < 4; ++ks) {
            const int kk = ks << 4;
            uint32_t af[2][4], ag[2][4], bf[4][4];

            // B-hi fragments (4 x n16)
#pragma unroll
            for (int nq = 0; nq < 4; ++nq)
                LDSM4(bf[nq], sBh + (uint32_t)((b_row + (nq << 4)) * PADK + kk + b_koff) * 2);
            // A-hi, A-lo fragments (2 x m16 each)
#pragma unroll
            for (int mi = 0; mi < 2; ++mi) {
                LDSM4(af[mi], sAh + (uint32_t)((a_row + (mi << 4)) * PADK + kk + a_koff) * 2);
                LDSM4(ag[mi], sAl + (uint32_t)((a_row + (mi << 4)) * PADK + kk + a_koff) * 2);
            }
            // Ah*Bh and Al*Bh
#pragma unroll
            for (int mi = 0; mi < 2; ++mi)
#pragma unroll
                for (int nq = 0; nq < 4; ++nq) {
                    MMA_BF16(acc[mi][2 * nq],     af[mi], bf[nq][0], bf[nq][1]);
                    MMA_BF16(acc[mi][2 * nq + 1], af[mi], bf[nq][2], bf[nq][3]);
                    MMA_BF16(acc[mi][2 * nq],     ag[mi], bf[nq][0], bf[nq][1]);
                    MMA_BF16(acc[mi][2 * nq + 1], ag[mi], bf[nq][2], bf[nq][3]);
                }
            // B-lo fragments (reuse bf regs), then Ah*Bl
#pragma unroll
            for (int nq = 0; nq < 4; ++nq)
                LDSM4(bf[nq], sBl + (uint32_t)((b_row + (nq << 4)) * PADK + kk + b_koff) * 2);
#pragma unroll
            for (int mi = 0; mi < 2; ++mi)
#pragma unroll
                for (int nq = 0; nq < 4; ++nq) {
                    MMA_BF16(acc[mi][2 * nq],     af[mi], bf[nq][0], bf[nq][1]);
                    MMA_BF16(acc[mi][2 * nq + 1], af[mi], bf[nq][2], bf[nq][3]);
                }
        }
        __syncthreads();
    }

    // epilogue
    const int r0 = bm + wm + (lane >> 2);
    const int c0 = bn + wn + ((lane & 3) << 1);
#pragma unroll
    for (int mi = 0; mi < 2; ++mi)
#pragma unroll
        for (int nf = 0; nf < 8; ++nf) {
            float2* p0 = (float2*)&C[(size_t)(r0 + (mi << 4)) * N + c0 + nf * 8];
            float2* p1 = (float2*)&C[(size_t)(r0 + (mi << 4) + 8) * N + c0 + nf * 8];
            *p0 = make_float2(acc[mi][nf][0], acc[mi][nf][1]);
            *p1 = make_float2(acc[mi][nf][2], acc[mi][nf][3]);
        }
}

// ------------- RoPE + transpose: src[T][heads*128] -> dst[heads][128][T] --
__global__ __launch_bounds__(256) void rope_transpose(
    const float* __restrict__ src, float* __restrict__ dst,
    int heads, float scale)
{
    __shared__ float As[32][33];
    __shared__ float Bs[32][33];
    const int h  = blockIdx.z;
    const int t0 = blockIdx.x << 5;
    const int d0 = blockIdx.y << 5;          // 0 or 32 (within first half)
    const int tx  = threadIdx.x & 31;
    const int tyb = threadIdx.x >> 5;        // 0..7
    const int stride = heads * HD;
#pragma unroll
    for (int it = 0; it < 4; ++it) {
        int r = tyb + (it << 3);
        const float* p = src + (size_t)(t0 + r) * stride + h * HD + d0 + tx;
        As[r][tx] = p[0];
        Bs[r][tx] = p[64];
    }
    __syncthreads();
#pragma unroll
    for (int it = 0; it < 4; ++it) {
        int dl = tyb + (it << 3);
        int d  = d0 + dl;                    // 0..63
        int t  = t0 + tx;
        float inv_freq = powf(10000.0f, -(float)d * (1.0f / 64.0f));
        float ang = (float)t * inv_freq;
        float s, c;
        sincosf(ang, &s, &c);
        float x1 = As[tx][dl];
        float x2 = Bs[tx][dl];
        dst[(size_t)(h * HD + d)      * T_SEQ + t] = (x1 * c - x2 * s) * scale;
        dst[(size_t)(h * HD + d + 64) * T_SEQ + t] = (x1 * s + x2 * c) * scale;
    }
}

// ---------------- flash attention, sliding window + causal ---------------
#define PADQ 68
#define ATTN_SMEM ((128 * PADQ + 128 * PADQ + 64 * HD + 64 * PADQ) * 4)

__device__ __forceinline__ float rmax16(float v) {
    v = fmaxf(v, __shfl_xor_sync(0xffffffffu, v, 8));
    v = fmaxf(v, __shfl_xor_sync(0xffffffffu, v, 4));
    v = fmaxf(v, __shfl_xor_sync(0xffffffffu, v, 2));
    v = fmaxf(v, __shfl_xor_sync(0xffffffffu, v, 1));
    return v;
}
__device__ __forceinline__ float rsum16(float v) {
    v += __shfl_xor_sync(0xffffffffu, v, 8);
    v += __shfl_xor_sync(0xffffffffu, v, 4);
    v += __shfl_xor_sync(0xffffffffu, v, 2);
    v += __shfl_xor_sync(0xffffffffu, v, 1);
    return v;
}

__global__ __launch_bounds__(256) void attn_kernel(
    const float* __restrict__ Qt,   // [QH][HD][T]
    const float* __restrict__ Kt,   // [KVH][HD][T]
    const float* __restrict__ V,    // [T][KVH*HD]
    float* __restrict__ O)          // [T][QH*HD]
{
    extern __shared__ float sm[];
    float* Qs = sm;                 // [128][PADQ]  (d-major)
    float* Ks = Qs + 128 * PADQ;    // [128][PADQ]
    float* Vs = Ks + 128 * PADQ;    // [64][128]    (row-major)
    float* Ps = Vs + 64 * HD;       // [64][PADQ]

    const int h  = blockIdx.y;
    const int g  = h >> 2;          // kv head (reps = 4)
    const int qs = blockIdx.x << 6;
    const int tid = threadIdx.x;
    const int tx = tid & 15, ty = tid >> 4;

    // load Q tile: Qs[d][r] = Qt[h][d][qs+r]
    const float* qbase = Qt + (size_t)h * HD * T_SEQ + qs;
    for (int i = tid; i < 128 * 16; i += 256) {
        int d = i >> 4, r4 = (i & 15) << 2;
        *(float4*)&Qs[d * PADQ + r4] = *(const float4*)(qbase + (size_t)d * T_SEQ + r4);
    }

    float m[4], l[4], o[4][8];
#pragma unroll
    for (int i = 0; i < 4; ++i) {
        m[i] = -1e30f; l[i] = 0.f;
#pragma unroll
        for (int jj = 0; jj < 8; ++jj) o[i][jj] = 0.f;
    }

    const int kb0 = (qs >= WIN) ? ((qs - WIN) >> 6) : 0;
    const int kb1 = qs >> 6;

    for (int kb = kb0; kb <= kb1; ++kb) {
        const int ks0 = kb << 6;
        __syncthreads();   // prior PV reads done before Ks/Vs overwrite
        const float* kbase = Kt + (size_t)g * HD * T_SEQ + ks0;
        for (int i = tid; i < 128 * 16; i += 256) {
            int d = i >> 4, r4 = (i & 15) << 2;
            *(float4*)&Ks[d * PADQ + r4] = *(const float4*)(kbase + (size_t)d * T_SEQ + r4);
        }
        const float* vbase = V + (size_t)ks0 * (KVH * HD) + g * HD;
        for (int i = tid; i < 64 * 32; i += 256) {
            int r = i >> 5, d4 = (i & 31) << 2;
            *(float4*)&Vs[r * HD + d4] = *(const float4*)(vbase + (size_t)r * (KVH * HD) + d4);
        }
        __syncthreads();

        // S = Q.K^T (64x64), 4x4 fragment per thread
        float s[4][4];
#pragma unroll
        for (int i = 0; i < 4; ++i)
#pragma unroll
            for (int j = 0; j < 4; ++j) s[i][j] = 0.f;
#pragma unroll 4
        for (int k = 0; k < HD; ++k) {
            float a[4], b[4];
            *(float4*)a = *(const float4*)&Qs[k * PADQ + (ty << 2)];
            *(float4*)b = *(const float4*)&Ks[k * PADQ + (tx << 2)];
#pragma unroll
            for (int i = 0; i < 4; ++i)
#pragma unroll
                for (int j = 0; j < 4; ++j)
                    s[i][j] = fmaf(a[i], b[j], s[i][j]);
        }

        // mask + online softmax
#pragma unroll
        for (int i = 0; i < 4; ++i) {
            const int t = qs + (ty << 2) + i;
            float rm = -1e30f;
#pragma unroll
            for (int j = 0; j < 4; ++j) {
                int kj = ks0 + (tx << 2) + j;
                bool valid = (kj <= t) && (t - kj <= WIN);
                if (!valid) s[i][j] = -1e30f;
                rm = fmaxf(rm, s[i][j]);
            }
            rm = rmax16(rm);
            float mn   = fmaxf(m[i], rm);
            float corr = __expf(m[i] - mn);
            float sum = 0.f;
#pragma unroll
            for (int j = 0; j < 4; ++j) {
                float p = (s[i][j] > -1e29f) ? __expf(s[i][j] - mn) : 0.f;
                Ps[((ty << 2) + i) * PADQ + (tx << 2) + j] = p;
                sum += p;
            }
            sum = rsum16(sum);
            l[i] = l[i] * corr + sum;
            m[i] = mn;
#pragma unroll
            for (int jj = 0; jj < 8; ++jj) o[i][jj] *= corr;
        }
        __syncthreads();

        // O += P.V  (rows ty*4+i, dims tx*8+jj)
#pragma unroll 2
        for (int j = 0; j < 64; ++j) {
            float v[8];
            *(float4*)&v[0] = *(const float4*)&Vs[j * HD + (tx << 3)];
            *(float4*)&v[4] = *(const float4*)&Vs[j * HD + (tx << 3) + 4];
#pragma unroll
            for (int i = 0; i < 4; ++i) {
                float p = Ps[((ty << 2) + i) * PADQ + j];
#pragma unroll
                for (int jj = 0; jj < 8; ++jj)
                    o[i][jj] = fmaf(p, v[jj], o[i][jj]);
            }
        }
    }

#pragma unroll
    for (int i = 0; i < 4; ++i) {
        float inv = 1.0f / l[i];
        int t = qs + (ty << 2) + i;
        float* op = O + (size_t)t * HID + h * HD + (tx << 3);
        *(float4*)op       = make_float4(o[i][0] * inv, o[i][1] * inv, o[i][2] * inv, o[i][3] * inv);
        *(float4*)(op + 4) = make_float4(o[i][4] * inv, o[i][5] * inv, o[i][6] * inv, o[i][7] * inv);
    }
}

// --------------------------------------------------------------------------
extern "C" void kernel_launch(void* const* d_in, const int* in_sizes, int n_in,
                              void* d_out, int out_size)
{
    const float* x  = (const float*)d_in[0];
    const float* wq = (const float*)d_in[1];
    const float* wk = (const float*)d_in[2];
    const float* wv = (const float*)d_in[3];
    const float* wo = (const float*)d_in[4];
    float* out = (float*)d_out;

    float *qraw, *kraw, *v, *qt, *kt, *ao;
    cudaGetSymbolAddress((void**)&qraw, g_Qraw);
    cudaGetSymbolAddress((void**)&kraw, g_Kraw);
    cudaGetSymbolAddress((void**)&v,    g_V);
    cudaGetSymbolAddress((void**)&qt,   g_Qt);
    cudaGetSymbolAddress((void**)&kt,   g_Kt);
    cudaGetSymbolAddress((void**)&ao,   g_AO);

    __nv_bfloat16 *xh, *xl, *wqh, *wql, *wkh, *wkl, *wvh, *wvl, *woh, *wol, *aoh, *aol;
    cudaGetSymbolAddress((void**)&xh,  g_xh);  cudaGetSymbolAddress((void**)&xl,  g_xl);
    cudaGetSymbolAddress((void**)&wqh, g_wqh); cudaGetSymbolAddress((void**)&wql, g_wql);
    cudaGetSymbolAddress((void**)&wkh, g_wkh); cudaGetSymbolAddress((void**)&wkl, g_wkl);
    cudaGetSymbolAddress((void**)&wvh, g_wvh); cudaGetSymbolAddress((void**)&wvl, g_wvl);
    cudaGetSymbolAddress((void**)&woh, g_woh); cudaGetSymbolAddress((void**)&wol, g_wol);
    cudaGetSymbolAddress((void**)&aoh, g_aoh); cudaGetSymbolAddress((void**)&aol, g_aol);

    cudaFuncSetAttribute(attn_kernel,
                         cudaFuncAttributeMaxDynamicSharedMemorySize, ATTN_SMEM);
    cudaFuncSetAttribute(gemm_tc,
                         cudaFuncAttributeMaxDynamicSharedMemorySize, SMEM_TC);

    dim3 blk(256);
    const int nX  = T_SEQ * HID / 4;
    const int nWq = HID * HID / 4;
    const int nWk = KVH * HD * HID / 4;

    // split conversions
    split_bf16<<<(nX  + 255) / 256, blk>>>((const float4*)x,  (__nv_bfloat162*)xh,  (__nv_bfloat162*)xl,  nX);
    split_bf16<<<(nWq + 255) / 256, blk>>>((const float4*)wq, (__nv_bfloat162*)wqh, (__nv_bfloat162*)wql, nWq);
    split_bf16<<<(nWk + 255) / 256, blk>>>((const float4*)wk, (__nv_bfloat162*)wkh, (__nv_bfloat162*)wkl, nWk);
    split_bf16<<<(nWk + 255) / 256, blk>>>((const float4*)wv, (__nv_bfloat162*)wvh, (__nv_bfloat162*)wvl, nWk);
    split_bf16<<<(nWq + 255) / 256, blk>>>((const float4*)wo, (__nv_bfloat162*)woh, (__nv_bfloat162*)wol, nWq);

    // projections on tensor cores
    gemm_tc<<<dim3(HID / 128,      T_SEQ / 128), blk, SMEM_TC>>>(xh, xl, wqh, wql, qraw, T_SEQ, HID,      HID);
    gemm_tc<<<dim3(KVH * HD / 128, T_SEQ / 128), blk, SMEM_TC>>>(xh, xl, wkh, wkl, kraw, T_SEQ, KVH * HD, HID);
    gemm_tc<<<dim3(KVH * HD / 128, T_SEQ / 128), blk, SMEM_TC>>>(xh, xl, wvh, wvl, v,    T_SEQ, KVH * HD, HID);

    // RoPE + transpose (scale 1/sqrt(HD) folded into Q)
    rope_transpose<<<dim3(T_SEQ / 32, 2, QH),  blk>>>(qraw, qt, QH,  0.08838834764831845f);
    rope_transpose<<<dim3(T_SEQ / 32, 2, KVH), blk>>>(kraw, kt, KVH, 1.0f);

    // attention
    attn_kernel<<<dim3(T_SEQ / 64, QH), blk, ATTN_SMEM>>>(qt, kt, v, ao);

    // output projection
    split_bf16<<<(nX + 255) / 256, blk>>>((const float4*)ao, (__nv_bfloat162*)aoh, (__nv_bfloat162*)aol, nX);
    gemm_tc<<<dim3(HID / 128, T_SEQ / 128), blk, SMEM_TC>>>(aoh, aol, woh, wol, out, T_SEQ, HID, HID);
}

// round 11
// speedup vs baseline: 2.7518x; 1.4819x over previous
#include <cuda_runtime.h>
#include <cuda_bf16.h>
#include <math.h>
#include <stdint.h>

#define T_SEQ 4096
#define HID   2048
#define QH    16
#define KVH   4
#define HD    128
#define WIN   512
#define NQKV  3072          // 2048 q + 512 k + 512 v

// ---------------- scratch (device globals; no allocations allowed) --------
__device__ float g_QKV[T_SEQ * NQKV];                    // fused qkv proj out
__device__ __nv_bfloat16 g_xh [T_SEQ * HID],  g_xl [T_SEQ * HID];
__device__ __nv_bfloat16 g_wh [NQKV * HID],   g_wl [NQKV * HID];   // wq|wk|wv
__device__ __nv_bfloat16 g_woh[HID * HID],    g_wol[HID * HID];
__device__ __nv_bfloat16 g_Qh [QH  * T_SEQ * HD], g_Ql [QH  * T_SEQ * HD]; // [h][t][d]
__device__ __nv_bfloat16 g_Kh [KVH * T_SEQ * HD], g_Kl [KVH * T_SEQ * HD]; // [g][t][d]
__device__ __nv_bfloat16 g_Vth[KVH * HD * T_SEQ], g_Vtl[KVH * HD * T_SEQ]; // [g][d][t]
__device__ __nv_bfloat16 g_aoh[T_SEQ * HID],  g_aol[T_SEQ * HID];  // [t][h*128+d]

// ---------------- helpers -------------------------------------------------
__device__ __forceinline__ void cp16(uint32_t dst, const void* src) {
    asm volatile("cp.async.cg.shared.global [%0], [%1], 16;\n" :: "r"(dst), "l"(src));
}
#define CP_COMMIT() asm volatile("cp.async.commit_group;\n")
#define CP_WAIT0()  asm volatile("cp.async.wait_group 0;\n")

#define LDSM4(r, addr) \
    asm volatile("ldmatrix.sync.aligned.m8n8.x4.shared.b16 {%0,%1,%2,%3}, [%4];" \
        : "=r"((r)[0]), "=r"((r)[1]), "=r"((r)[2]), "=r"((r)[3]) : "r"(addr))

#define MMA_BF16(d, a, b0, b1) \
    asm volatile("mma.sync.aligned.m16n8k16.row.col.f32.bf16.bf16.f32 " \
        "{%0,%1,%2,%3}, {%4,%5,%6,%7}, {%8,%9}, {%0,%1,%2,%3};" \
        : "+f"((d)[0]), "+f"((d)[1]), "+f"((d)[2]), "+f"((d)[3]) \
        : "r"((a)[0]), "r"((a)[1]), "r"((a)[2]), "r"((a)[3]), "r"(b0), "r"(b1))

// pack two floats -> bf16x2 reg (low = v0, high = v1)
__device__ __forceinline__ uint32_t pkbf2(float v0, float v1) {
    uint32_t r;
    asm("cvt.rn.bf16x2.f32 %0, %1, %2;" : "=r"(r) : "f"(v1), "f"(v0));
    return r;
}

// ---------------- split fp32 -> bf16 hi + bf16 lo -------------------------
__global__ __launch_bounds__(256) void split_bf16(
    const float4* __restrict__ src,
    __nv_bfloat162* __restrict__ hi, __nv_bfloat162* __restrict__ lo, int n4)
{
    int i = blockIdx.x * blockDim.x + threadIdx.x;
    if (i >= n4) return;
    float4 f = src[i];
    uint32_t h0 = pkbf2(f.x, f.y), h1 = pkbf2(f.z, f.w);
    ((uint32_t*)hi)[2 * i] = h0; ((uint32_t*)hi)[2 * i + 1] = h1;
    float r0 = f.x - __uint_as_float(h0 << 16);
    float r1 = f.y - __uint_as_float(h0 & 0xffff0000u);
    float r2 = f.z - __uint_as_float(h1 << 16);
    float r3 = f.w - __uint_as_float(h1 & 0xffff0000u);
    ((uint32_t*)lo)[2 * i] = pkbf2(r0, r1); ((uint32_t*)lo)[2 * i + 1] = pkbf2(r2, r3);
}

// ---------------- tensor-core GEMM: C[M,N] = A[M,K] * B[N,K]^T ------------
#define PADK 72
#define TILE_BYTES (128 * PADK * 2)
#define STAGE_BYTES (4 * TILE_BYTES)
#define SMEM_TC (2 * STAGE_BYTES)

__global__ __launch_bounds__(256) void gemm_tc(
    const __nv_bfloat16* __restrict__ Ah, const __nv_bfloat16* __restrict__ Al,
    const __nv_bfloat16* __restrict__ Bh, const __nv_bfloat16* __restrict__ Bl,
    float* __restrict__ C, int M, int N, int K)
{
    extern __shared__ char smem_raw[];
    const uint32_t smem_base = (uint32_t)__cvta_generic_to_shared(smem_raw);
    const int tid = threadIdx.x;
    const int lane = tid & 31, warp = tid >> 5;
    const int wm = (warp >> 1) << 5;
    const int wn = (warp & 1) << 6;
    const int bm = blockIdx.y << 7, bn = blockIdx.x << 7;

    const int lrow = tid >> 3;
    const int lcol = (tid & 7) << 3;

    const __nv_bfloat16* pAh = Ah + (size_t)(bm + lrow) * K + lcol;
    const __nv_bfloat16* pAl = Al + (size_t)(bm + lrow) * K + lcol;
    const __nv_bfloat16* pBh = Bh + (size_t)(bn + lrow) * K + lcol;
    const __nv_bfloat16* pBl = Bl + (size_t)(bn + lrow) * K + lcol;
    const uint32_t sdst0 = smem_base + (uint32_t)(lrow * PADK + lcol) * 2;

    float acc[2][8][4];
#pragma unroll
    for (int i = 0; i < 2; ++i)
#pragma unroll
        for (int j = 0; j < 8; ++j)
#pragma unroll
            for (int q = 0; q < 4; ++q) acc[i][j][q] = 0.f;

    const int nkb = K >> 6;
    {
        uint32_t sb = sdst0;
#pragma unroll
        for (int p = 0; p < 4; ++p) {
            size_t go = (size_t)(p << 5) * K;
            uint32_t so = sb + (uint32_t)(p << 5) * PADK * 2;
            cp16(so + 0 * TILE_BYTES, pAh + go);
            cp16(so + 1 * TILE_BYTES, pAl + go);
            cp16(so + 2 * TILE_BYTES, pBh + go);
            cp16(so + 3 * TILE_BYTES, pBl + go);
        }
        CP_COMMIT();
    }

    const int a_row  = wm + (lane & 15);
    const int a_koff = (lane >> 4) << 3;
    const int b_row  = wn + (lane & 7) + ((lane & 16) >> 1);
    const int b_koff = ((lane >> 3) & 1) << 3;

    for (int kb = 0; kb < nkb; ++kb) {
        CP_WAIT0();
        __syncthreads();

        if (kb + 1 < nkb) {
            const int k0 = (kb + 1) << 6;
            uint32_t sb = sdst0 + ((kb + 1) & 1) * STAGE_BYTES;
#pragma unroll
            for (int p = 0; p < 4; ++p) {
                size_t go = (size_t)(p << 5) * K + k0;
                uint32_t so = sb + (uint32_t)(p << 5) * PADK * 2;
                cp16(so + 0 * TILE_BYTES, pAh + go);
                cp16(so + 1 * TILE_BYTES, pAl + go);
                cp16(so + 2 * TILE_BYTES, pBh + go);
                cp16(so + 3 * TILE_BYTES, pBl + go);
            }
            CP_COMMIT();
        }

        const uint32_t sb  = smem_base + (kb & 1) * STAGE_BYTES;
        const uint32_t sAh = sb;
        const uint32_t sAl = sb + 1 * TILE_BYTES;
        const uint32_t sBh = sb + 2 * TILE_BYTES;
        const uint32_t sBl = sb + 3 * TILE_BYTES;

#pragma unroll
        for (int ks = 0; ks < 4; ++ks) {
            const int kk = ks << 4;
            uint32_t af[2][4], ag[2][4], bf[4][4];
#pragma unroll
            for (int nq = 0; nq < 4; ++nq)
                LDSM4(bf[nq], sBh + (uint32_t)((b_row + (nq << 4)) * PADK + kk + b_koff) * 2);
#pragma unroll
            for (int mi = 0; mi < 2; ++mi) {
                LDSM4(af[mi], sAh + (uint32_t)((a_row + (mi << 4)) * PADK + kk + a_koff) * 2);
                LDSM4(ag[mi], sAl + (uint32_t)((a_row + (mi << 4)) * PADK + kk + a_koff) * 2);
            }
#pragma unroll
            for (int mi = 0; mi < 2; ++mi)
#pragma unroll
                for (int nq = 0; nq < 4; ++nq) {
                    MMA_BF16(acc[mi][2 * nq],     af[mi], bf[nq][0], bf[nq][1]);
                    MMA_BF16(acc[mi][2 * nq + 1], af[mi], bf[nq][2], bf[nq][3]);
                    MMA_BF16(acc[mi][2 * nq],     ag[mi], bf[nq][0], bf[nq][1]);
                    MMA_BF16(acc[mi][2 * nq + 1], ag[mi], bf[nq][2], bf[nq][3]);
                }
#pragma unroll
            for (int nq = 0; nq < 4; ++nq)
                LDSM4(bf[nq], sBl + (uint32_t)((b_row + (nq << 4)) * PADK + kk + b_koff) * 2);
#pragma unroll
            for (int mi = 0; mi < 2; ++mi)
#pragma unroll
                for (int nq = 0; nq < 4; ++nq) {
                    MMA_BF16(acc[mi][2 * nq],     af[mi], bf[nq][0], bf[nq][1]);
                    MMA_BF16(acc[mi][2 * nq + 1], af[mi], bf[nq][2], bf[nq][3]);
                }
        }
        __syncthreads();
    }

    const int r0 = bm + wm + (lane >> 2);
    const int c0 = bn + wn + ((lane & 3) << 1);
#pragma unroll
    for (int mi = 0; mi < 2; ++mi)
#pragma unroll
        for (int nf = 0; nf < 8; ++nf) {
            float2* p0 = (float2*)&C[(size_t)(r0 + (mi << 4)) * N + c0 + nf * 8];
            float2* p1 = (float2*)&C[(size_t)(r0 + (mi << 4) + 8) * N + c0 + nf * 8];
            *p0 = make_float2(acc[mi][nf][0], acc[mi][nf][1]);
            *p1 = make_float2(acc[mi][nf][2], acc[mi][nf][3]);
        }
}

// ------------- RoPE -> bf16 hi/lo, [h][t][d] layout -----------------------
// head < QH : Q (scale = log2e / sqrt(HD));  head >= QH : K (scale = 1)
__global__ __launch_bounds__(256) void rope_split(
    const float* __restrict__ qkv,
    __nv_bfloat16* __restrict__ Qh_, __nv_bfloat16* __restrict__ Ql_,
    __nv_bfloat16* __restrict__ Kh_, __nv_bfloat16* __restrict__ Kl_)
{
    const int d = threadIdx.x & 63;
    const int t = (blockIdx.x << 2) + (threadIdx.x >> 6);
    const int head = blockIdx.y;

    float scale; int col; __nv_bfloat16 *dh, *dl; size_t dbase;
    if (head < QH) {
        scale = 0.1275174476f;           // log2e / sqrt(128)
        col = head * HD + d;
        dh = Qh_; dl = Ql_;
        dbase = ((size_t)head * T_SEQ + t) * HD + d;
    } else {
        scale = 1.0f;
        int g = head - QH;
        col = HID + g * HD + d;
        dh = Kh_; dl = Kl_;
        dbase = ((size_t)g * T_SEQ + t) * HD + d;
    }
    float x1 = qkv[(size_t)t * NQKV + col];
    float x2 = qkv[(size_t)t * NQKV + col + 64];
    float inv_freq = powf(10000.0f, -(float)d * (1.0f / 64.0f));
    float ang = (float)t * inv_freq;
    float s, c;
    sincosf(ang, &s, &c);
    float o1 = (x1 * c - x2 * s) * scale;
    float o2 = (x1 * s + x2 * c) * scale;

    __nv_bfloat16 h1 = __float2bfloat16(o1);
    __nv_bfloat16 h2 = __float2bfloat16(o2);
    dh[dbase]      = h1;
    dh[dbase + 64] = h2;
    dl[dbase]      = __float2bfloat16(o1 - __bfloat162float(h1));
    dl[dbase + 64] = __float2bfloat16(o2 - __bfloat162float(h2));
}

// ------------- V: [t][2560+g*128+d] fp32 -> [g][d][t] bf16 hi/lo ----------
__global__ __launch_bounds__(256) void v_transpose(
    const float* __restrict__ qkv,
    __nv_bfloat16* __restrict__ Vth_, __nv_bfloat16* __restrict__ Vtl_)
{
    __shared__ float tile[32][33];
    const int g  = blockIdx.z;
    const int t0 = blockIdx.x << 5;
    const int d0 = blockIdx.y << 5;
    const int tx = threadIdx.x & 31;
    const int ty = threadIdx.x >> 5;
#pragma unroll
    for (int j = 0; j < 4; ++j) {
        int r = ty + (j << 3);
        tile[r][tx] = qkv[(size_t)(t0 + r) * NQKV + HID + KVH * HD + g * HD + d0 + tx];
    }
    __syncthreads();
#pragma unroll
    for (int j = 0; j < 4; ++j) {
        int dl = ty + (j << 3);
        float v = tile[tx][dl];
        __nv_bfloat16 h = __float2bfloat16(v);
        size_t idx = ((size_t)g * HD + d0 + dl) * T_SEQ + t0 + tx;
        Vth_[idx] = h;
        Vtl_[idx] = __float2bfloat16(v - __bfloat162float(h));
    }
}

// ---------------- tensor-core flash attention -----------------------------
// grid (T/128, QH), 256 threads. bf16 hi/lo 3-product for S and PV.
#define BM 128
#define BN 64
#define PADD 136    // row stride for [.][128] bf16 tiles
#define PADT 72     // row stride for [128][64] Vt tiles
#define SQH 0
#define SQL (128 * PADD)
#define SKH (2 * 128 * PADD)
#define SKL (SKH + 64 * PADD)
#define SVH (SKL + 64 * PADD)
#define SVL (SVH + 128 * PADT)
#define ATTN_SMEM ((SVL + 128 * PADT) * 2)

__global__ __launch_bounds__(256) void attn_tc(
    const __nv_bfloat16* __restrict__ Qh_, const __nv_bfloat16* __restrict__ Ql_,
    const __nv_bfloat16* __restrict__ Kh_, const __nv_bfloat16* __restrict__ Kl_,
    const __nv_bfloat16* __restrict__ Vth_, const __nv_bfloat16* __restrict__ Vtl_,
    __nv_bfloat16* __restrict__ Oh, __nv_bfloat16* __restrict__ Ol)
{
    extern __shared__ char smraw[];
    const uint32_t sb = (uint32_t)__cvta_generic_to_shared(smraw);
    const int h  = blockIdx.y;
    const int g  = h >> 2;
    const int qs = blockIdx.x << 7;
    const int tid = threadIdx.x;
    const int lane = tid & 31, warp = tid >> 5;
    const int wm = warp << 4;

    // ---- prologue: Q tile (128x128 hi+lo) via cp.async ----
    {
        const __nv_bfloat16* qh_g = Qh_ + ((size_t)h * T_SEQ + qs) * HD;
        const __nv_bfloat16* ql_g = Ql_ + ((size_t)h * T_SEQ + qs) * HD;
        const int r = tid >> 4, c = (tid & 15) << 3;
#pragma unroll
        for (int p = 0; p < 8; ++p) {
            int rr = r + (p << 4);
            cp16(sb + (uint32_t)(SQH + rr * PADD + c) * 2, qh_g + (size_t)rr * HD + c);
            cp16(sb + (uint32_t)(SQL + rr * PADD + c) * 2, ql_g + (size_t)rr * HD + c);
        }
        CP_COMMIT();
    }

    float m[2] = {-1e30f, -1e30f}, l[2] = {0.f, 0.f};
    float oacc[16][4];
#pragma unroll
    for (int i = 0; i < 16; ++i)
#pragma unroll
        for (int e = 0; e < 4; ++e) oacc[i][e] = 0.f;

    const int kb0 = (qs >= WIN) ? ((qs - WIN) >> 6) : 0;
    const int kb1 = (qs + BM - 1) >> 6;

    // fragment address components
    const uint32_t aq_h = sb + (uint32_t)(SQH + (wm + (lane & 15)) * PADD + ((lane >> 4) << 3)) * 2;
    const uint32_t aq_l = sb + (uint32_t)(SQL + (wm + (lane & 15)) * PADD + ((lane >> 4) << 3)) * 2;
    const int b_row  = (lane & 7) + ((lane & 16) >> 1);
    const int b_koff = ((lane >> 3) & 1) << 3;

    for (int kb = kb0; kb <= kb1; ++kb) {
        const int ks0 = kb << 6;
        __syncthreads();
        {
            const __nv_bfloat16* kh_g = Kh_ + ((size_t)g * T_SEQ + ks0) * HD;
            const __nv_bfloat16* kl_g = Kl_ + ((size_t)g * T_SEQ + ks0) * HD;
            const int r = tid >> 4, c = (tid & 15) << 3;
#pragma unroll
            for (int p = 0; p < 4; ++p) {
                int rr = r + (p << 4);
                cp16(sb + (uint32_t)(SKH + rr * PADD + c) * 2, kh_g + (size_t)rr * HD + c);
                cp16(sb + (uint32_t)(SKL + rr * PADD + c) * 2, kl_g + (size_t)rr * HD + c);
            }
            const __nv_bfloat16* vh_g = Vth_ + (size_t)g * HD * T_SEQ + ks0;
            const __nv_bfloat16* vl_g = Vtl_ + (size_t)g * HD * T_SEQ + ks0;
            const int vr = tid >> 3, vc = (tid & 7) << 3;
#pragma unroll
            for (int p = 0; p < 4; ++p) {
                int rr = vr + (p << 5);
                cp16(sb + (uint32_t)(SVH + rr * PADT + vc) * 2, vh_g + (size_t)rr * T_SEQ + vc);
                cp16(sb + (uint32_t)(SVL + rr * PADT + vc) * 2, vl_g + (size_t)rr * T_SEQ + vc);
            }
            CP_COMMIT();
        }
        CP_WAIT0();
        __syncthreads();

        // ---- S = Q K^T (warp: 16 x 64), 3-product ----
        float sacc[8][4];
#pragma unroll
        for (int i = 0; i < 8; ++i)
#pragma unroll
            for (int e = 0; e < 4; ++e) sacc[i][e] = 0.f;

#pragma unroll
        for (int ks = 0; ks < 8; ++ks) {
            const int kk = ks << 4;
            uint32_t afh[4], afl[4];
            LDSM4(afh, aq_h + kk * 2);
            LDSM4(afl, aq_l + kk * 2);
#pragma unroll
            for (int nq = 0; nq < 4; ++nq) {
                uint32_t bk[4];
                LDSM4(bk, sb + (uint32_t)(SKH + (b_row + (nq << 4)) * PADD + kk + b_koff) * 2);
                MMA_BF16(sacc[2 * nq],     afh, bk[0], bk[1]);
                MMA_BF16(sacc[2 * nq + 1], afh, bk[2], bk[3]);
                MMA_BF16(sacc[2 * nq],     afl, bk[0], bk[1]);
                MMA_BF16(sacc[2 * nq + 1], afl, bk[2], bk[3]);
                LDSM4(bk, sb + (uint32_t)(SKL + (b_row + (nq << 4)) * PADD + kk + b_koff) * 2);
                MMA_BF16(sacc[2 * nq],     afh, bk[0], bk[1]);
                MMA_BF16(sacc[2 * nq + 1], afh, bk[2], bk[3]);
            }
        }

        // ---- mask ----
        const int q0 = qs + wm + (lane >> 2);
        const bool full = (ks0 + BN - 1 <= qs + wm) && ((qs + wm + 15) - ks0 <= WIN);
        if (!full) {
#pragma unroll
            for (int nf = 0; nf < 8; ++nf)
#pragma unroll
                for (int e = 0; e < 4; ++e) {
                    int q = q0 + ((e >> 1) << 3);
                    int k = ks0 + nf * 8 + ((lane & 3) << 1) + (e & 1);
                    if (k > q || q - k > WIN) sacc[nf][e] = -1e30f;
                }
        }

        // ---- online softmax (rows i = 0: lanes' row, 1: +8) ----
#pragma unroll
        for (int i = 0; i < 2; ++i) {
            float rm = -1e30f;
#pragma unroll
            for (int nf = 0; nf < 8; ++nf)
                rm = fmaxf(rm, fmaxf(sacc[nf][2 * i], sacc[nf][2 * i + 1]));
            rm = fmaxf(rm, __shfl_xor_sync(0xffffffffu, rm, 1));
            rm = fmaxf(rm, __shfl_xor_sync(0xffffffffu, rm, 2));
            float mn = fmaxf(m[i], rm);
            float corr = exp2f(m[i] - mn);
            float sum = 0.f;
#pragma unroll
            for (int nf = 0; nf < 8; ++nf)
#pragma unroll
                for (int par = 0; par < 2; ++par) {
                    float sv = sacc[nf][2 * i + par];
                    float p = (sv < -1e29f) ? 0.f : exp2f(sv - mn);
                    sacc[nf][2 * i + par] = p;
                    sum += p;
                }
            sum += __shfl_xor_sync(0xffffffffu, sum, 1);
            sum += __shfl_xor_sync(0xffffffffu, sum, 2);
            l[i] = l[i] * corr + sum;
            m[i] = mn;
#pragma unroll
            for (int nf = 0; nf < 16; ++nf) {
                oacc[nf][2 * i]     *= corr;
                oacc[nf][2 * i + 1] *= corr;
            }
        }

        // ---- pack P -> bf16 hi/lo A fragments (k16 groups) ----
        uint32_t ph[4][4], pl[4][4];
#pragma unroll
        for (int kk = 0; kk < 4; ++kk)
#pragma unroll
            for (int j = 0; j < 4; ++j) {
                int frag = 2 * kk + (j >> 1);
                int eb = (j & 1) << 1;
                float v0 = sacc[frag][eb], v1 = sacc[frag][eb + 1];
                uint32_t hp = pkbf2(v0, v1);
                ph[kk][j] = hp;
                float r0 = v0 - __uint_as_float(hp << 16);
                float r1 = v1 - __uint_as_float(hp & 0xffff0000u);
                pl[kk][j] = pkbf2(r0, r1);
            }

        // ---- O += P V (warp: 16 x 128), 3-product ----
        const int vrow = (lane & 7) + ((lane & 16) >> 1);
        const int vkoff = ((lane >> 3) & 1) << 3;
#pragma unroll
        for (int kk = 0; kk < 4; ++kk) {
            const int kko = kk << 4;
#pragma unroll
            for (int nv = 0; nv < 8; ++nv) {
                uint32_t vb[4];
                LDSM4(vb, sb + (uint32_t)(SVH + (vrow + (nv << 4)) * PADT + kko + vkoff) * 2);
                MMA_BF16(oacc[2 * nv],     ph[kk], vb[0], vb[1]);
                MMA_BF16(oacc[2 * nv + 1], ph[kk], vb[2], vb[3]);
                MMA_BF16(oacc[2 * nv],     pl[kk], vb[0], vb[1]);
                MMA_BF16(oacc[2 * nv + 1], pl[kk], vb[2], vb[3]);
                LDSM4(vb, sb + (uint32_t)(SVL + (vrow + (nv << 4)) * PADT + kko + vkoff) * 2);
                MMA_BF16(oacc[2 * nv],     ph[kk], vb[0], vb[1]);
                MMA_BF16(oacc[2 * nv + 1], ph[kk], vb[2], vb[3]);
            }
        }
    }

    // ---- epilogue: normalize, split to bf16 hi/lo, write ao ----
    const float inv0 = 1.0f / l[0], inv1 = 1.0f / l[1];
    const int t0 = qs + wm + (lane >> 2);
    const int cb = h * HD + ((lane & 3) << 1);
#pragma unroll
    for (int nf = 0; nf < 16; ++nf) {
        int c = cb + nf * 8;
        {
            float v0 = oacc[nf][0] * inv0, v1 = oacc[nf][1] * inv0;
            uint32_t hp = pkbf2(v0, v1);
            float r0 = v0 - __uint_as_float(hp << 16);
            float r1 = v1 - __uint_as_float(hp & 0xffff0000u);
            *(uint32_t*)&Oh[(size_t)t0 * HID + c] = hp;
            *(uint32_t*)&Ol[(size_t)t0 * HID + c] = pkbf2(r0, r1);
        }
        {
            float v0 = oacc[nf][2] * inv1, v1 = oacc[nf][3] * inv1;
            uint32_t hp = pkbf2(v0, v1);
            float r0 = v0 - __uint_as_float(hp << 16);
            float r1 = v1 - __uint_as_float(hp & 0xffff0000u);
            *(uint32_t*)&Oh[(size_t)(t0 + 8) * HID + c] = hp;
            *(uint32_t*)&Ol[(size_t)(t0 + 8) * HID + c] = pkbf2(r0, r1);
        }
    }
}

// --------------------------------------------------------------------------
extern "C" void kernel_launch(void* const* d_in, const int* in_sizes, int n_in,
                              void* d_out, int out_size)
{
    const float* x  = (const float*)d_in[0];
    const float* wq = (const float*)d_in[1];
    const float* wk = (const float*)d_in[2];
    const float* wv = (const float*)d_in[3];
    const float* wo = (const float*)d_in[4];
    float* out = (float*)d_out;

    float* qkv;
    cudaGetSymbolAddress((void**)&qkv, g_QKV);
    __nv_bfloat16 *xh, *xl, *wh, *wl, *woh, *wol;
    __nv_bfloat16 *qh, *ql, *kh, *kl, *vth, *vtl, *aoh, *aol;
    cudaGetSymbolAddress((void**)&xh,  g_xh);  cudaGetSymbolAddress((void**)&xl,  g_xl);
    cudaGetSymbolAddress((void**)&wh,  g_wh);  cudaGetSymbolAddress((void**)&wl,  g_wl);
    cudaGetSymbolAddress((void**)&woh, g_woh); cudaGetSymbolAddress((void**)&wol, g_wol);
    cudaGetSymbolAddress((void**)&qh,  g_Qh);  cudaGetSymbolAddress((void**)&ql,  g_Ql);
    cudaGetSymbolAddress((void**)&kh,  g_Kh);  cudaGetSymbolAddress((void**)&kl,  g_Kl);
    cudaGetSymbolAddress((void**)&vth, g_Vth); cudaGetSymbolAddress((void**)&vtl, g_Vtl);
    cudaGetSymbolAddress((void**)&aoh, g_aoh); cudaGetSymbolAddress((void**)&aol, g_aol);

    cudaFuncSetAttribute(gemm_tc,
                         cudaFuncAttributeMaxDynamicSharedMemorySize, SMEM_TC);
    cudaFuncSetAttribute(attn_tc,
                         cudaFuncAttributeMaxDynamicSharedMemorySize, ATTN_SMEM);

    dim3 blk(256);
    const int nX  = T_SEQ * HID / 4;
    const int nWq = HID * HID / 4;
    const int nWk = KVH * HD * HID / 4;
    const size_t oK = (size_t)HID * HID;              // wk offset in concat
    const size_t oV = oK + (size_t)KVH * HD * HID;    // wv offset

    // split conversions (wq|wk|wv concatenated into g_wh/g_wl)
    split_bf16<<<(nX  + 255) / 256, blk>>>((const float4*)x,  (__nv_bfloat162*)xh, (__nv_bfloat162*)xl, nX);
    split_bf16<<<(nWq + 255) / 256, blk>>>((const float4*)wq, (__nv_bfloat162*)wh, (__nv_bfloat162*)wl, nWq);
    split_bf16<<<(nWk + 255) / 256, blk>>>((const float4*)wk, (__nv_bfloat162*)(wh + oK), (__nv_bfloat162*)(wl + oK), nWk);
    split_bf16<<<(nWk + 255) / 256, blk>>>((const float4*)wv, (__nv_bfloat162*)(wh + oV), (__nv_bfloat162*)(wl + oV), nWk);
    split_bf16<<<(nWq + 255) / 256, blk>>>((const float4*)wo, (__nv_bfloat162*)woh, (__nv_bfloat162*)wol, nWq);

    // fused QKV projection
    gemm_tc<<<dim3(NQKV / 128, T_SEQ / 128), blk, SMEM_TC>>>(xh, xl, wh, wl, qkv, T_SEQ, NQKV, HID);

    // RoPE + split (Q scaled by log2e/sqrt(HD)); V transpose + split
    rope_split<<<dim3(T_SEQ / 4, QH + KVH), blk>>>(qkv, qh, ql, kh, kl);
    v_transpose<<<dim3(T_SEQ / 32, HD / 32, KVH), blk>>>(qkv, vth, vtl);

    // tensor-core attention -> bf16 hi/lo ao
    attn_tc<<<dim3(T_SEQ / BM, QH), blk, ATTN_SMEM>>>(qh, ql, kh, kl, vth, vtl, aoh, aol);

    // output projection
    gemm_tc<<<dim3(HID / 128, T_SEQ / 128), blk, SMEM_TC>>>(aoh, aol, woh, wol, out, T_SEQ, HID, HID);
}